// round 2
// baseline (speedup 1.0000x reference)
#include <cuda_runtime.h>
#include <math.h>

#define T_STEPS 256
#define BB      32
#define NI      28
#define NH      1024
#define NO      10
#define GRID    128
#define MT      8        // output rows (i) per CTA
#define NTH     256
#define TWO_PI_F 6.283185307179586f

// ---- persistent device scratch (no allocs allowed) ----
__device__ float d_P[(size_t)T_STEPS * NH * BB];   // [t][h][b] = Wi(x) + Wi_b + omega
__device__ float d_V[2][NH][64];                   // [ping][j][n]: n<32 -> cos(s[b=n][j]); n>=32 -> sin(s[b=n-32][j])
__device__ float d_state[BB * NH];                 // [b][h] final state
__device__ unsigned g_bar;

// ---------------- prep: input projection + omega fold, V init, barrier reset ----------------
__global__ void prep_kernel(const float* __restrict__ x,
                            const float* __restrict__ Wi_w,
                            const float* __restrict__ Wi_b,
                            const float* __restrict__ omega) {
    const int bid = blockIdx.x;          // = t*BB + b
    const int t = bid >> 5;
    const int b = bid & 31;
    __shared__ float xs[NI];
    if (threadIdx.x < NI) xs[threadIdx.x] = x[(size_t)bid * NI + threadIdx.x];
    if (bid == 0 && threadIdx.x == 0) g_bar = 0u;
    // init V ping buffer for state0 = 0: cos = 1, sin = 0
    if (bid < NH && threadIdx.x < 64) {
        d_V[0][bid][threadIdx.x] = (threadIdx.x < 32) ? 1.0f : 0.0f;
    }
    __syncthreads();
#pragma unroll
    for (int k = 0; k < NH / NTH; ++k) {
        const int h = threadIdx.x + k * NTH;
        float acc = Wi_b[h] + omega[h];
        const float* wr = Wi_w + (size_t)h * NI;
#pragma unroll
        for (int i = 0; i < NI; ++i) acc = fmaf(xs[i], wr[i], acc);
        d_P[((size_t)t * NH + h) * BB + b] = acc;
    }
}

// ---------------- grid barrier (monotonic counter, reset by prep_kernel) ----------------
__device__ __forceinline__ void grid_bar(unsigned target) {
    __syncthreads();
    if (threadIdx.x == 0) {
        __threadfence();
        atomicAdd(&g_bar, 1u);
        while (*(volatile unsigned*)&g_bar < target) { }
        __threadfence();
    }
    __syncthreads();
}

// ---------------- persistent scan kernel ----------------
__global__ void __launch_bounds__(NTH, 1)
scan_kernel(const float* __restrict__ Wh,
            const float* __restrict__ W_out,
            const float* __restrict__ b_out,
            float* __restrict__ out) {
    __shared__ float WhT[NH * MT];    // transposed [j][r], 32KB, resident all steps
    __shared__ float red[8 * 512];    // per-warp partial C tiles, 16KB

    const int tid = threadIdx.x;
    const int cta = blockIdx.x;
    const int i0  = cta * MT;

    // load this CTA's 8 rows of Wh, transposed: WhT[j*8 + r] = Wh[i0+r][j]
    for (int idx = tid; idx < NH * MT; idx += NTH) {
        const int j = idx >> 3, r = idx & 7;
        WhT[idx] = Wh[(size_t)(i0 + r) * NH + j];
    }

    const int w    = tid >> 5;        // warp 0..7 (K-split)
    const int l    = tid & 31;
    const int iGrp = l >> 3;          // 0..3 -> rows {2*iGrp, 2*iGrp+1}
    const int nGrp = l & 7;           // 0..7 -> cols [8*nGrp, 8*nGrp+8)

    // state ownership: thread -> (b, i)
    const int b  = tid & 31;
    const int ii = tid >> 5;
    const int i  = i0 + ii;

    float s = 0.0f, s_sin = 0.0f, s_cos = 1.0f;

    __syncthreads();

    unsigned target = 0;
    int ping = 0;

    for (int t = 0; t < T_STEPS; ++t) {
        const float p = __ldg(&d_P[((size_t)t * NH + i) * BB + b]);

        // ---- GEMM: C[i_local, n] += Wh[i, j] * V[j, n], warp handles K-slice of 128 ----
        float acc[2][8];
#pragma unroll
        for (int aa = 0; aa < 2; ++aa)
#pragma unroll
            for (int c = 0; c < 8; ++c) acc[aa][c] = 0.0f;

        const float* Vb   = &d_V[ping][0][0] + (size_t)(w * 128) * 64 + nGrp * 8;
        const float* WhTp = &WhT[(w * 128) * MT + iGrp * 2];

#pragma unroll 8
        for (int jj = 0; jj < 128; ++jj) {
            const float2 a  = *(const float2*)WhTp;
            const float4 v0 = __ldcg((const float4*)Vb);
            const float4 v1 = __ldcg((const float4*)(Vb + 4));
            acc[0][0] = fmaf(a.x, v0.x, acc[0][0]);
            acc[0][1] = fmaf(a.x, v0.y, acc[0][1]);
            acc[0][2] = fmaf(a.x, v0.z, acc[0][2]);
            acc[0][3] = fmaf(a.x, v0.w, acc[0][3]);
            acc[0][4] = fmaf(a.x, v1.x, acc[0][4]);
            acc[0][5] = fmaf(a.x, v1.y, acc[0][5]);
            acc[0][6] = fmaf(a.x, v1.z, acc[0][6]);
            acc[0][7] = fmaf(a.x, v1.w, acc[0][7]);
            acc[1][0] = fmaf(a.y, v0.x, acc[1][0]);
            acc[1][1] = fmaf(a.y, v0.y, acc[1][1]);
            acc[1][2] = fmaf(a.y, v0.z, acc[1][2]);
            acc[1][3] = fmaf(a.y, v0.w, acc[1][3]);
            acc[1][4] = fmaf(a.y, v1.x, acc[1][4]);
            acc[1][5] = fmaf(a.y, v1.y, acc[1][5]);
            acc[1][6] = fmaf(a.y, v1.z, acc[1][6]);
            acc[1][7] = fmaf(a.y, v1.w, acc[1][7]);
            WhTp += MT;
            Vb   += 64;
        }

        // ---- store per-warp partials, cross-warp reduce ----
        {
            const int base = w * 512 + (iGrp * 2) * 64 + nGrp * 8;
#pragma unroll
            for (int aa = 0; aa < 2; ++aa)
#pragma unroll
                for (int c = 0; c < 8; ++c)
                    red[base + aa * 64 + c] = acc[aa][c];
        }
        __syncthreads();
        {
            float s0 = 0.0f, s1 = 0.0f;
#pragma unroll
            for (int ww = 0; ww < 8; ++ww) {
                s0 += red[ww * 512 + tid];
                s1 += red[ww * 512 + tid + 256];
            }
            red[tid]       = s0;   // reduced C lives in red[0..511]
            red[tid + 256] = s1;
        }
        __syncthreads();

        // ---- state update for this thread's (b, i) ----
        {
            const float Ccos = red[ii * 64 + b];        // (Wh * cos)_i for batch b
            const float Csin = red[ii * 64 + 32 + b];   // (Wh * sin)_i for batch b
            const float coup = s_sin * Ccos - s_cos * Csin;
            const float xv   = coup + p + s;
            float ns = fmodf(xv, TWO_PI_F);
            if (ns < 0.0f) ns += TWO_PI_F;
            s = ns;
            sincosf(s, &s_sin, &s_cos);
            const int np = ping ^ 1;
            d_V[np][i][b]      = s_cos;
            d_V[np][i][32 + b] = s_sin;
            ping = np;
        }

        target += GRID;
        grid_bar(target);
    }

    // ---- final state out + readout ----
    d_state[b * NH + i] = s;
    grid_bar(target + GRID);

    if (cta == 0) {
        for (int pair = w; pair < BB * NO; pair += 8) {
            const int bb = pair / NO, oo = pair % NO;
            float acc = 0.0f;
            for (int h = l; h < NH; h += 32)
                acc = fmaf(__ldcg(&d_state[bb * NH + h]), W_out[(size_t)oo * NH + h], acc);
#pragma unroll
            for (int off = 16; off; off >>= 1)
                acc += __shfl_down_sync(0xffffffffu, acc, off);
            if (l == 0) out[bb * NO + oo] = acc + b_out[oo];
        }
    }
}

extern "C" void kernel_launch(void* const* d_in, const int* in_sizes, int n_in,
                              void* d_out, int out_size) {
    const float* x     = (const float*)d_in[0];
    const float* Wi_w  = (const float*)d_in[1];
    const float* Wi_b  = (const float*)d_in[2];
    const float* Wh    = (const float*)d_in[3];
    const float* omega = (const float*)d_in[4];
    const float* W_out = (const float*)d_in[5];
    const float* b_out = (const float*)d_in[6];
    float* out = (float*)d_out;

    prep_kernel<<<T_STEPS * BB, NTH>>>(x, Wi_w, Wi_b, omega);
    scan_kernel<<<GRID, NTH>>>(Wh, W_out, b_out, out);
}

// round 3
// speedup vs baseline: 1.7670x; 1.7670x over previous
#include <cuda_runtime.h>
#include <math.h>

#define T_STEPS 256
#define BB      32
#define NI      28
#define NH      1024
#define NO      10
#define GRID    128
#define NTH     256
#define IT      32        // rows (i) per CTA
#define NBT     4         // batch tiles
#define CB      16        // V columns per CTA (8 batches x {cos,sin})
#define TWO_PI_F 6.283185307179586f

typedef unsigned long long ull;

// ---- persistent device scratch ----
__device__ float d_P[(size_t)T_STEPS * NH * BB];    // [t][h][b]
__device__ float d_V[2][NBT][NH][CB];               // [ping][btile][j][col], col = lb*2 + {0=cos,1=sin}
__device__ float d_state[BB * NH];                  // [b][h]
__device__ unsigned g_bar;

// packed f32x2 helpers (ptxas never auto-fuses these)
#define PACK2(d,a,b) asm("mov.b64 %0, {%1, %2};" : "=l"(d) : "f"(a), "f"(b))
#define FMA2(d,a,b,c) asm("fma.rn.f32x2 %0, %1, %2, %3;" : "=l"(d) : "l"(a), "l"(b), "l"(c))
#define ADD2(d,a,b)  asm("add.rn.f32x2 %0, %1, %2;" : "=l"(d) : "l"(a), "l"(b))

// ---------------- prep: input projection + omega fold, V init, barrier reset ----------------
__global__ void prep_kernel(const float* __restrict__ x,
                            const float* __restrict__ Wi_w,
                            const float* __restrict__ Wi_b,
                            const float* __restrict__ omega) {
    const int bid = blockIdx.x;          // = t*BB + b
    const int t = bid >> 5;
    const int b = bid & 31;
    __shared__ float xs[NI];
    if (threadIdx.x < NI) xs[threadIdx.x] = x[(size_t)bid * NI + threadIdx.x];
    if (bid == 0 && threadIdx.x == 0) g_bar = 0u;
    // init V ping buffer for state0 = 0: cos = 1 (even cols), sin = 0 (odd cols)
    if (bid < (NBT * NH * CB) / NTH) {
        const int idx = bid * NTH + threadIdx.x;
        ((float*)d_V)[idx] = (idx & 1) ? 0.0f : 1.0f;
    }
    __syncthreads();
#pragma unroll
    for (int k = 0; k < NH / NTH; ++k) {
        const int h = threadIdx.x + k * NTH;
        float acc = Wi_b[h] + omega[h];
        const float* wr = Wi_w + (size_t)h * NI;
#pragma unroll
        for (int i = 0; i < NI; ++i) acc = fmaf(xs[i], wr[i], acc);
        d_P[((size_t)t * NH + h) * BB + b] = acc;
    }
}

// ---------------- grid barrier (monotonic counter) ----------------
__device__ __forceinline__ void grid_bar(unsigned target) {
    __syncthreads();
    if (threadIdx.x == 0) {
        __threadfence();
        atomicAdd(&g_bar, 1u);
        while (*(volatile unsigned*)&g_bar < target) { }
        __threadfence();
    }
    __syncthreads();
}

// ---------------- persistent scan kernel ----------------
// smem: WhT [1024][32] f32 (128KB) | Vs [1024][16] f32 (64KB) | red ull[8][16][16] (16KB) | redF ull[16][16] (2KB)
#define SMEM_FLOATS (NH*IT + NH*CB)
#define SMEM_BYTES  (SMEM_FLOATS*4 + 8*16*16*8 + 16*16*8)

extern __shared__ float smem[];

__global__ void __launch_bounds__(NTH, 1)
scan_kernel(const float* __restrict__ Wh,
            const float* __restrict__ W_out,
            const float* __restrict__ b_out,
            float* __restrict__ out) {
    float* WhT = smem;                    // WhT[j*32 + r] = Wh[i0+r][j]
    float* Vs  = smem + NH * IT;          // Vs[j*16 + c]
    ull*   red  = (ull*)(smem + SMEM_FLOATS);  // red[(w*16+rpg)*16 + c]
    ull*   redF = red + 8 * 16 * 16;           // redF[rpg*16 + c]

    const int tid = threadIdx.x;
    const int cta = blockIdx.x;
    const int it  = cta >> 2;            // i-tile 0..31
    const int bt  = cta & 3;             // batch-tile 0..3
    const int i0  = it * IT;

    // fill WhT (one-time; coalesced global reads)
    for (int idx = tid; idx < NH * IT; idx += NTH) {
        const int r = idx >> 10, j = idx & 1023;
        WhT[j * IT + r] = Wh[(size_t)(i0 + r) * NH + j];
    }

    // GEMM lane mapping: warp w owns K-slice [w*128, w*128+128)
    const int w    = tid >> 5;
    const int l    = tid & 31;
    const int rGrp = l >> 3;             // 4 groups x 8 rows
    const int cGrp = l & 7;              // 8 groups x 2 cols

    // state ownership: thread -> (i_loc, lb)
    const int i_loc = tid >> 3;          // 0..31
    const int lb    = tid & 7;           // 0..7
    const int h     = i0 + i_loc;
    const int b     = bt * 8 + lb;

    float s = 0.0f, s_sin = 0.0f, s_cos = 1.0f;

    __syncthreads();

    unsigned target = 0;
    int ping = 0;

    for (int t = 0; t < T_STEPS; ++t) {
        // ---- stage this CTA's V slice (64KB, contiguous) into smem ----
        {
            const float4* src = (const float4*)&d_V[ping][bt][0][0];
            float4* dst = (float4*)Vs;
            float4 tmp[8];
#pragma unroll
            for (int k = 0; k < 8; ++k) tmp[k] = __ldcg(src + tid + k * NTH);
#pragma unroll
            for (int k = 0; k < 8; ++k) dst[tid + k * NTH] = tmp[k];
#pragma unroll
            for (int k = 0; k < 8; ++k) tmp[k] = __ldcg(src + tid + (k + 8) * NTH);
#pragma unroll
            for (int k = 0; k < 8; ++k) dst[tid + (k + 8) * NTH] = tmp[k];
        }
        const float p = __ldg(&d_P[((size_t)t * NH + h) * BB + b]);
        __syncthreads();

        // ---- GEMM: C[32][16] += WhT[j][:] * Vs[j][:], warp K-split, f32x2 packed ----
        ull acc[4][2];
#pragma unroll
        for (int rp = 0; rp < 4; ++rp) { acc[rp][0] = 0ull; acc[rp][1] = 0ull; }

        const float* Wp = WhT + (w * 128) * IT + rGrp * 8;
        const float* Vp = Vs  + (w * 128) * CB + cGrp * 2;

#pragma unroll 4
        for (int jj = 0; jj < 128; ++jj) {
            const float4 wa = *(const float4*)Wp;
            const float4 wb = *(const float4*)(Wp + 4);
            const float2 v  = *(const float2*)Vp;
            ull dvx, dvy, a0, a1, a2, a3;
            PACK2(dvx, v.x, v.x); PACK2(dvy, v.y, v.y);
            PACK2(a0, wa.x, wa.y); PACK2(a1, wa.z, wa.w);
            PACK2(a2, wb.x, wb.y); PACK2(a3, wb.z, wb.w);
            FMA2(acc[0][0], a0, dvx, acc[0][0]); FMA2(acc[0][1], a0, dvy, acc[0][1]);
            FMA2(acc[1][0], a1, dvx, acc[1][0]); FMA2(acc[1][1], a1, dvy, acc[1][1]);
            FMA2(acc[2][0], a2, dvx, acc[2][0]); FMA2(acc[2][1], a2, dvy, acc[2][1]);
            FMA2(acc[3][0], a3, dvx, acc[3][0]); FMA2(acc[3][1], a3, dvy, acc[3][1]);
            Wp += IT; Vp += CB;
        }

        // ---- cross-warp K reduction (b64 pairs = row pairs) ----
#pragma unroll
        for (int rp = 0; rp < 4; ++rp) {
            red[(w * 16 + rGrp * 4 + rp) * 16 + cGrp * 2 + 0] = acc[rp][0];
            red[(w * 16 + rGrp * 4 + rp) * 16 + cGrp * 2 + 1] = acc[rp][1];
        }
        __syncthreads();
        {
            const int rpg = tid >> 4, c = tid & 15;
            ull sacc = red[rpg * 16 + c];
#pragma unroll
            for (int ww = 1; ww < 8; ++ww) ADD2(sacc, sacc, red[(ww * 16 + rpg) * 16 + c]);
            redF[rpg * 16 + c] = sacc;
        }
        __syncthreads();

        // ---- state update for (b, h) ----
        {
            const float* rf = (const float*)redF;
            const int rp = i_loc >> 1, half = i_loc & 1;
            const float Ccos = rf[(rp * 16 + 2 * lb) * 2 + half];
            const float Csin = rf[(rp * 16 + 2 * lb + 1) * 2 + half];
            const float coup = s_sin * Ccos - s_cos * Csin;
            const float xv   = coup + p + s;
            float ns = fmodf(xv, TWO_PI_F);
            if (ns < 0.0f) ns += TWO_PI_F;
            s = ns;
            sincosf(s, &s_sin, &s_cos);
            const int np = ping ^ 1;
            *(float2*)&d_V[np][bt][h][2 * lb] = make_float2(s_cos, s_sin);
            ping = np;
        }

        target += GRID;
        grid_bar(target);
    }

    // ---- final state out + readout ----
    d_state[b * NH + h] = s;
    grid_bar(target + GRID);

    if (cta == 0) {
        for (int pair = w; pair < BB * NO; pair += 8) {
            const int bb = pair / NO, oo = pair % NO;
            float acc = 0.0f;
            for (int hh = l; hh < NH; hh += 32)
                acc = fmaf(__ldcg(&d_state[bb * NH + hh]), W_out[(size_t)oo * NH + hh], acc);
#pragma unroll
            for (int off = 16; off; off >>= 1)
                acc += __shfl_down_sync(0xffffffffu, acc, off);
            if (l == 0) out[bb * NO + oo] = acc + b_out[oo];
        }
    }
}

extern "C" void kernel_launch(void* const* d_in, const int* in_sizes, int n_in,
                              void* d_out, int out_size) {
    const float* x     = (const float*)d_in[0];
    const float* Wi_w  = (const float*)d_in[1];
    const float* Wi_b  = (const float*)d_in[2];
    const float* Wh    = (const float*)d_in[3];
    const float* omega = (const float*)d_in[4];
    const float* W_out = (const float*)d_in[5];
    const float* b_out = (const float*)d_in[6];
    float* out = (float*)d_out;

    cudaFuncSetAttribute(scan_kernel, cudaFuncAttributeMaxDynamicSharedMemorySize, SMEM_BYTES);

    prep_kernel<<<T_STEPS * BB, NTH>>>(x, Wi_w, Wi_b, omega);
    scan_kernel<<<GRID, NTH, SMEM_BYTES>>>(Wh, W_out, b_out, out);
}

// round 5
// speedup vs baseline: 1.8303x; 1.0359x over previous
#include <cuda_runtime.h>
#include <math.h>

#define T_STEPS 256
#define BB      32
#define NI      28
#define NH      1024
#define NO      10
#define GRID    128
#define NTH     256
#define IT      32        // rows (i) per CTA
#define NBT     4         // batch tiles
#define CB      16        // V columns per CTA (8 batches x {cos,sin})
#define TWO_PI_F 6.283185307179586f
#define INV_TWO_PI_F 0.15915494309189535f

typedef unsigned long long ull;

// ---- persistent device scratch ----
__device__ float d_P[(size_t)T_STEPS * NH * BB];    // [t][h][b]
__device__ float d_V[2][NBT][NH][CB];               // [ping][btile][j][col]
__device__ float d_state[BB * NH];                  // [b][h]
__device__ unsigned g_bar4[NBT * 32];               // per-group counters, 128B apart
__device__ unsigned g_bar;                          // final one-shot barrier

// packed f32x2 helpers
#define PACK2(d,a,b) asm("mov.b64 %0, {%1, %2};" : "=l"(d) : "f"(a), "f"(b))
#define FMA2(d,a,b,c) asm("fma.rn.f32x2 %0, %1, %2, %3;" : "=l"(d) : "l"(a), "l"(b), "l"(c))
#define ADD2(d,a,b)  asm("add.rn.f32x2 %0, %1, %2;" : "=l"(d) : "l"(a), "l"(b))

// ---------------- prep ----------------
__global__ void prep_kernel(const float* __restrict__ x,
                            const float* __restrict__ Wi_w,
                            const float* __restrict__ Wi_b,
                            const float* __restrict__ omega) {
    const int bid = blockIdx.x;          // = t*BB + b
    const int t = bid >> 5;
    const int b = bid & 31;
    __shared__ float xs[NI];
    if (threadIdx.x < NI) xs[threadIdx.x] = x[(size_t)bid * NI + threadIdx.x];
    if (bid == 0) {
        if (threadIdx.x == 0) g_bar = 0u;
        if (threadIdx.x < NBT * 32) g_bar4[threadIdx.x] = 0u;
    }
    // init V ping buffer for state0 = 0: cos = 1 (even cols), sin = 0 (odd cols)
    if (bid < (NBT * NH * CB) / NTH) {
        const int idx = bid * NTH + threadIdx.x;
        ((float*)d_V)[idx] = (idx & 1) ? 0.0f : 1.0f;
    }
    __syncthreads();
#pragma unroll
    for (int k = 0; k < NH / NTH; ++k) {
        const int h = threadIdx.x + k * NTH;
        float acc = Wi_b[h] + omega[h];
        const float* wr = Wi_w + (size_t)h * NI;
#pragma unroll
        for (int i = 0; i < NI; ++i) acc = fmaf(xs[i], wr[i], acc);
        d_P[((size_t)t * NH + h) * BB + b] = acc;
    }
}

// ---------------- proven atomic+spin barrier, scoped to a counter ----------------
__device__ __forceinline__ void bar_on(unsigned* ctr, unsigned target) {
    __syncthreads();
    if (threadIdx.x == 0) {
        __threadfence();
        atomicAdd(ctr, 1u);
        while (*(volatile unsigned*)ctr < target) { }
        __threadfence();
    }
    __syncthreads();
}

// ---------------- persistent scan kernel ----------------
// smem: WhT [1024][32] (128KB) | Vs [1024][16] (64KB) | red ull[8][16][17] (17KB) | redF ull[16][16] (2KB)
#define RED_STRIDE 17
#define SMEM_FLOATS (NH*IT + NH*CB)
#define SMEM_BYTES  (SMEM_FLOATS*4 + 8*16*RED_STRIDE*8 + 16*16*8)

extern __shared__ float smem[];

__global__ void __launch_bounds__(NTH, 1)
scan_kernel(const float* __restrict__ Wh,
            const float* __restrict__ W_out,
            const float* __restrict__ b_out,
            float* __restrict__ out) {
    float* WhT = smem;                          // WhT[j*32 + r] = Wh[i0+r][j]
    float* Vs  = smem + NH * IT;                // Vs[j*16 + c], per-warp K-slices
    ull*   red  = (ull*)(smem + SMEM_FLOATS);   // red[(w*16+RP)*17 + col]
    ull*   redF = red + 8 * 16 * RED_STRIDE;    // redF[RP*16 + col]

    const int tid = threadIdx.x;
    const int cta = blockIdx.x;
    const int it  = cta >> 2;            // i-tile 0..31
    const int bt  = cta & 3;             // batch-tile 0..3
    const int i0  = it * IT;

    // one-time fill of WhT (coalesced global reads)
    for (int idx = tid; idx < NH * IT; idx += NTH) {
        const int r = idx >> 10, j = idx & 1023;
        WhT[j * IT + r] = Wh[(size_t)(i0 + r) * NH + j];
    }

    const int w  = tid >> 5;             // warp: K-slice [w*128, w*128+128)
    const int l  = tid & 31;
    const int rg = l & 7;                // 8 row-groups x 4 rows
    const int cg = l >> 3;               // 4 col-groups x 4 cols

    const int i_loc = tid >> 3;          // 0..31
    const int lb    = tid & 7;           // 0..7
    const int h     = i0 + i_loc;
    const int b     = bt * 8 + lb;

    float s = 0.0f, s_sin = 0.0f, s_cos = 1.0f;

    __syncthreads();

    int ping = 0;
    unsigned target = 0;

    for (int t = 0; t < T_STEPS; ++t) {
        const float p = __ldg(&d_P[((size_t)t * NH + h) * BB + b]);

        // ---- per-warp stage of this warp's V slice (8KB) into smem ----
        {
            const float4* src = (const float4*)(&d_V[ping][bt][0][0]) + w * 512;
            float4* dst = (float4*)(Vs + w * 128 * CB);
            float4 tmp[8];
#pragma unroll
            for (int k = 0; k < 8; ++k) tmp[k] = __ldcg(src + l + k * 32);
#pragma unroll
            for (int k = 0; k < 8; ++k) dst[l + k * 32] = tmp[k];
#pragma unroll
            for (int k = 0; k < 8; ++k) tmp[k] = __ldcg(src + l + (k + 8) * 32);
#pragma unroll
            for (int k = 0; k < 8; ++k) dst[l + (k + 8) * 32] = tmp[k];
        }
        __syncwarp();

        // ---- GEMM: warp K-split, thread tile 4 rows x 4 cols, f32x2 packed ----
        ull acc[2][4];
#pragma unroll
        for (int c = 0; c < 4; ++c) { acc[0][c] = 0ull; acc[1][c] = 0ull; }

        const float* Wp = WhT + (w * 128) * IT + rg * 4;
        const float* Vp = Vs  + (w * 128) * CB + cg * 4;

#pragma unroll 4
        for (int jj = 0; jj < 128; ++jj) {
            const ulonglong2 w4 = *(const ulonglong2*)Wp;   // rows rg*4..rg*4+3 (2 pairs)
            const float4     v4 = *(const float4*)Vp;       // cols cg*4..cg*4+3
            ull dv0, dv1, dv2, dv3;
            PACK2(dv0, v4.x, v4.x); PACK2(dv1, v4.y, v4.y);
            PACK2(dv2, v4.z, v4.z); PACK2(dv3, v4.w, v4.w);
            FMA2(acc[0][0], w4.x, dv0, acc[0][0]); FMA2(acc[1][0], w4.y, dv0, acc[1][0]);
            FMA2(acc[0][1], w4.x, dv1, acc[0][1]); FMA2(acc[1][1], w4.y, dv1, acc[1][1]);
            FMA2(acc[0][2], w4.x, dv2, acc[0][2]); FMA2(acc[1][2], w4.y, dv2, acc[1][2]);
            FMA2(acc[0][3], w4.x, dv3, acc[0][3]); FMA2(acc[1][3], w4.y, dv3, acc[1][3]);
            Wp += IT;   // next j row (32 floats)
            Vp += CB;   // next j row (16 floats)
        }

        // ---- cross-warp K reduction ----
#pragma unroll
        for (int rp = 0; rp < 2; ++rp)
#pragma unroll
            for (int c = 0; c < 4; ++c)
                red[(w * 16 + rg * 2 + rp) * RED_STRIDE + cg * 4 + c] = acc[rp][c];
        __syncthreads();
        {
            const int RP = tid >> 4, col = tid & 15;
            ull sacc = red[RP * RED_STRIDE + col];
#pragma unroll
            for (int ww = 1; ww < 8; ++ww)
                ADD2(sacc, sacc, red[(ww * 16 + RP) * RED_STRIDE + col]);
            redF[RP * 16 + col] = sacc;
        }
        __syncthreads();

        // ---- state update for (b, h) ----
        {
            const float* rf = (const float*)redF;
            const int rp = i_loc >> 1, half = i_loc & 1;
            const float Ccos = rf[(rp * 16 + 2 * lb) * 2 + half];
            const float Csin = rf[(rp * 16 + 2 * lb + 1) * 2 + half];
            const float coup = s_sin * Ccos - s_cos * Csin;
            const float xv   = coup + p + s;
            const float k    = floorf(xv * INV_TWO_PI_F);
            float ns = fmaf(-TWO_PI_F, k, xv);
            if (ns < 0.0f) ns += TWO_PI_F;
            else if (ns >= TWO_PI_F) ns -= TWO_PI_F;
            s = ns;
            __sincosf(s, &s_sin, &s_cos);
            const int np = ping ^ 1;
            *(float2*)&d_V[np][bt][h][2 * lb] = make_float2(s_cos, s_sin);
            ping = np;
        }

        // ---- group barrier: all 32 CTAs of this bt-group finished step t ----
        target += 32;
        bar_on(&g_bar4[bt * 32], target);
    }

    // ---- final state out + full-grid barrier + readout ----
    d_state[b * NH + h] = s;
    bar_on(&g_bar, GRID);

    if (cta == 0) {
        for (int pair = w; pair < BB * NO; pair += 8) {
            const int bb = pair / NO, oo = pair % NO;
            float acc = 0.0f;
            for (int hh = l; hh < NH; hh += 32)
                acc = fmaf(__ldcg(&d_state[bb * NH + hh]), W_out[(size_t)oo * NH + hh], acc);
#pragma unroll
            for (int off = 16; off; off >>= 1)
                acc += __shfl_down_sync(0xffffffffu, acc, off);
            if (l == 0) out[bb * NO + oo] = acc + b_out[oo];
        }
    }
}

extern "C" void kernel_launch(void* const* d_in, const int* in_sizes, int n_in,
                              void* d_out, int out_size) {
    const float* x     = (const float*)d_in[0];
    const float* Wi_w  = (const float*)d_in[1];
    const float* Wi_b  = (const float*)d_in[2];
    const float* Wh    = (const float*)d_in[3];
    const float* omega = (const float*)d_in[4];
    const float* W_out = (const float*)d_in[5];
    const float* b_out = (const float*)d_in[6];
    float* out = (float*)d_out;

    cudaFuncSetAttribute(scan_kernel, cudaFuncAttributeMaxDynamicSharedMemorySize, SMEM_BYTES);

    prep_kernel<<<T_STEPS * BB, NTH>>>(x, Wi_w, Wi_b, omega);
    scan_kernel<<<GRID, NTH, SMEM_BYTES>>>(Wh, W_out, b_out, out);
}